// round 2
// baseline (speedup 1.0000x reference)
#include <cuda_runtime.h>
#include <math.h>

// Problem constants
#define BATCH    4
#define SEQ      2048
#define DMODEL   1024
#define NHEADS   16
#define HDIM     64
#define INV_SCALE 0.125f   // 1/sqrt(64)
#define NEG_INF_F (-1e30f)

// Scratch (static __device__ arrays are the allowed scratch mechanism)
// layout: [B*H][S][64]
__device__ float g_q[(size_t)BATCH * NHEADS * SEQ * HDIM];
__device__ float g_k[(size_t)BATCH * NHEADS * SEQ * HDIM];
__device__ float g_v[(size_t)BATCH * NHEADS * SEQ * HDIM];
// attention output in (B, S, H, 64) == (B, S, D) layout
__device__ float g_attn[(size_t)BATCH * SEQ * DMODEL];

// ---------------------------------------------------------------------------
// Kernel 1: QKV projection.  C[8192,3072] = X[8192,1024] @ W[1024,3072],
// epilogue scatters into g_q / g_k / g_v with [B*H][S][64] layout.
// 128x128x8 tile, 256 threads, 8x8 microtile (strided 16-apart rows/cols).
// ---------------------------------------------------------------------------
__global__ __launch_bounds__(256) void qkv_gemm_kernel(
    const float* __restrict__ X, const float* __restrict__ W)
{
    const int K = DMODEL;          // 1024
    const int N = 3 * DMODEL;      // 3072

    __shared__ float As[8][128];
    __shared__ float Bs[8][128];

    int tid = threadIdx.x;
    int bm = blockIdx.y;           // 64 blocks of 128 rows
    int bn = blockIdx.x;           // 24 blocks of 128 cols

    int aRow = tid >> 1;           // 0..127
    int aCol = (tid & 1) * 4;      // 0 or 4
    int bRow = tid >> 5;           // 0..7
    int bCol = (tid & 31) * 4;     // 0..124

    const float* Aptr = X + (size_t)(bm * 128 + aRow) * K + aCol;
    const float* Bptr = W + (size_t)bRow * N + bn * 128 + bCol;

    int ty = tid >> 4;             // 0..15
    int tx = tid & 15;             // 0..15

    float acc[8][8];
#pragma unroll
    for (int i = 0; i < 8; i++)
#pragma unroll
        for (int j = 0; j < 8; j++) acc[i][j] = 0.f;

    for (int k0 = 0; k0 < K; k0 += 8) {
        float4 a4 = *(const float4*)(Aptr + k0);
        As[aCol + 0][aRow] = a4.x;
        As[aCol + 1][aRow] = a4.y;
        As[aCol + 2][aRow] = a4.z;
        As[aCol + 3][aRow] = a4.w;
        float4 b4 = *(const float4*)(Bptr + (size_t)k0 * N);
        *(float4*)&Bs[bRow][bCol] = b4;
        __syncthreads();

#pragma unroll
        for (int k = 0; k < 8; k++) {
            float ra[8], rb[8];
#pragma unroll
            for (int i = 0; i < 8; i++) ra[i] = As[k][i * 16 + ty];
#pragma unroll
            for (int j = 0; j < 8; j++) rb[j] = Bs[k][j * 16 + tx];
#pragma unroll
            for (int i = 0; i < 8; i++)
#pragma unroll
                for (int j = 0; j < 8; j++) acc[i][j] += ra[i] * rb[j];
        }
        __syncthreads();
    }

    // Epilogue: route column n -> (t, h, d); row m -> (b, s)
#pragma unroll
    for (int i = 0; i < 8; i++) {
        int m = bm * 128 + i * 16 + ty;
        int b = m >> 11;            // /2048
        int s = m & 2047;
#pragma unroll
        for (int j = 0; j < 8; j++) {
            int n = bn * 128 + j * 16 + tx;
            int t = n >> 10;        // 0=q, 1=k, 2=v
            int h = (n >> 6) & 15;
            int d = n & 63;
            float* dst = (t == 0) ? g_q : (t == 1) ? g_k : g_v;
            dst[(((size_t)(b * NHEADS + h) * SEQ) + s) * HDIM + d] = acc[i][j];
        }
    }
}

// ---------------------------------------------------------------------------
// Kernel 2: Flash attention (fp32, online softmax).
// grid = (S/64 = 32 query blocks, B*H = 64), block = 64 threads.
// Each thread owns one query row: q (64f) + acc (64f) in registers.
// K/V staged in SMEM in 32-key tiles, broadcast-read (conflict free).
// Causal: only visit key blocks <= diagonal (~52% of work).
// ---------------------------------------------------------------------------
__global__ __launch_bounds__(64) void flash_attn_kernel(const int* __restrict__ mask)
{
    __shared__ float Ks[32][64];
    __shared__ float Vs[32][64];
    __shared__ int   Ms[32];

    int tid = threadIdx.x;         // 0..63
    int qb  = blockIdx.x;          // query block
    int bh  = blockIdx.y;          // b*H + h
    int b   = bh >> 4;
    int h   = bh & 15;
    int r   = qb * 64 + tid;       // this thread's query row

    const float4* qptr = (const float4*)(g_q + ((size_t)bh * SEQ + r) * HDIM);
    float4 q[16];
#pragma unroll
    for (int i = 0; i < 16; i++) q[i] = qptr[i];

    float4 acc[16];
#pragma unroll
    for (int i = 0; i < 16; i++) acc[i] = make_float4(0.f, 0.f, 0.f, 0.f);

    float m_i = -1e38f;
    float l_i = 0.f;

    int nkb = qb * 2 + 2;          // 32-key blocks covering keys [0, (qb+1)*64)
    for (int kb = 0; kb < nkb; kb++) {
        int j0 = kb * 32;
        const float4* K4 = (const float4*)(g_k + ((size_t)bh * SEQ + j0) * HDIM);
        const float4* V4 = (const float4*)(g_v + ((size_t)bh * SEQ + j0) * HDIM);
#pragma unroll
        for (int i = 0; i < 8; i++) {
            int idx = i * 64 + tid;        // 512 float4 total
            ((float4*)Ks)[idx] = K4[idx];
            ((float4*)Vs)[idx] = V4[idx];
        }
        if (tid < 32) Ms[tid] = mask[b * SEQ + j0 + tid];
        __syncthreads();

        // scores for 32 keys
        float sc[32];
        float bmax = -1e38f;
#pragma unroll 4
        for (int j = 0; j < 32; j++) {
            const float4* kr = (const float4*)&Ks[j][0];
            float4 s4 = make_float4(0.f, 0.f, 0.f, 0.f);
#pragma unroll
            for (int i = 0; i < 16; i++) {
                float4 k4 = kr[i];
                s4.x += q[i].x * k4.x;
                s4.y += q[i].y * k4.y;
                s4.z += q[i].z * k4.z;
                s4.w += q[i].w * k4.w;
            }
            float s = (s4.x + s4.y) + (s4.z + s4.w);
            s *= INV_SCALE;
            int kj = j0 + j;
            if (kj > r || Ms[j] == 0) s = NEG_INF_F;  // causal + pad mask
            sc[j] = s;
            bmax = fmaxf(bmax, s);
        }

        float m_new = fmaxf(m_i, bmax);
        float scale = __expf(m_i - m_new);
        float lsum = 0.f;
#pragma unroll
        for (int j = 0; j < 32; j++) {
            float p = __expf(sc[j] - m_new);
            lsum += p;
            sc[j] = p;
        }
        l_i = l_i * scale + lsum;
#pragma unroll
        for (int i = 0; i < 16; i++) {
            acc[i].x *= scale; acc[i].y *= scale;
            acc[i].z *= scale; acc[i].w *= scale;
        }
#pragma unroll 4
        for (int j = 0; j < 32; j++) {
            float p = sc[j];
            const float4* vr = (const float4*)&Vs[j][0];
#pragma unroll
            for (int i = 0; i < 16; i++) {
                float4 v4 = vr[i];
                acc[i].x += p * v4.x;
                acc[i].y += p * v4.y;
                acc[i].z += p * v4.z;
                acc[i].w += p * v4.w;
            }
        }
        m_i = m_new;
        __syncthreads();
    }

    float inv_l = 1.f / l_i;
    // (B, S, H, 64) layout == (B, S, D) after flatten
    float4* optr = (float4*)(g_attn + (((size_t)b * SEQ + r) * NHEADS + h) * HDIM);
#pragma unroll
    for (int i = 0; i < 16; i++) {
        float4 o = acc[i];
        o.x *= inv_l; o.y *= inv_l; o.z *= inv_l; o.w *= inv_l;
        optr[i] = o;
    }
}

// ---------------------------------------------------------------------------
// Kernel 3: output projection. out[8192,1024] = g_attn[8192,1024] @ Wo[1024,1024]
// ---------------------------------------------------------------------------
__global__ __launch_bounds__(256) void proj_gemm_kernel(
    const float* __restrict__ W, float* __restrict__ out)
{
    const int K = DMODEL;          // 1024
    const int N = DMODEL;          // 1024

    __shared__ float As[8][128];
    __shared__ float Bs[8][128];

    int tid = threadIdx.x;
    int bm = blockIdx.y;           // 64
    int bn = blockIdx.x;           // 8

    int aRow = tid >> 1;
    int aCol = (tid & 1) * 4;
    int bRow = tid >> 5;
    int bCol = (tid & 31) * 4;

    const float* Aptr = g_attn + (size_t)(bm * 128 + aRow) * K + aCol;
    const float* Bptr = W + (size_t)bRow * N + bn * 128 + bCol;

    int ty = tid >> 4;
    int tx = tid & 15;

    float acc[8][8];
#pragma unroll
    for (int i = 0; i < 8; i++)
#pragma unroll
        for (int j = 0; j < 8; j++) acc[i][j] = 0.f;

    for (int k0 = 0; k0 < K; k0 += 8) {
        float4 a4 = *(const float4*)(Aptr + k0);
        As[aCol + 0][aRow] = a4.x;
        As[aCol + 1][aRow] = a4.y;
        As[aCol + 2][aRow] = a4.z;
        As[aCol + 3][aRow] = a4.w;
        float4 b4 = *(const float4*)(Bptr + (size_t)k0 * N);
        *(float4*)&Bs[bRow][bCol] = b4;
        __syncthreads();

#pragma unroll
        for (int k = 0; k < 8; k++) {
            float ra[8], rb[8];
#pragma unroll
            for (int i = 0; i < 8; i++) ra[i] = As[k][i * 16 + ty];
#pragma unroll
            for (int j = 0; j < 8; j++) rb[j] = Bs[k][j * 16 + tx];
#pragma unroll
            for (int i = 0; i < 8; i++)
#pragma unroll
                for (int j = 0; j < 8; j++) acc[i][j] += ra[i] * rb[j];
        }
        __syncthreads();
    }

#pragma unroll
    for (int i = 0; i < 8; i++) {
        int m = bm * 128 + i * 16 + ty;
#pragma unroll
        for (int j = 0; j < 8; j++) {
            int n = bn * 128 + j * 16 + tx;
            out[(size_t)m * N + n] = acc[i][j];
        }
    }
}

// ---------------------------------------------------------------------------
// Entry point
// ---------------------------------------------------------------------------
extern "C" void kernel_launch(void* const* d_in, const int* in_sizes, int n_in,
                              void* d_out, int out_size)
{
    const float* x      = (const float*)d_in[0];   // (4, 2048, 1024) fp32
    const int*   mask   = (const int*)d_in[1];     // (4, 2048) int32
    const float* w_qkv  = (const float*)d_in[2];   // (1024, 3072) fp32
    const float* w_out  = (const float*)d_in[3];   // (1024, 1024) fp32
    float*       out    = (float*)d_out;           // (4, 2048, 1024) fp32

    (void)in_sizes; (void)n_in; (void)out_size;

    // 1) QKV projection -> g_q/g_k/g_v in [B*H][S][64]
    qkv_gemm_kernel<<<dim3(24, 64), 256>>>(x, w_qkv);

    // 2) Causal flash attention -> g_attn in (B, S, D)
    flash_attn_kernel<<<dim3(32, 64), 64>>>(mask);

    // 3) Output projection -> d_out
    proj_gemm_kernel<<<dim3(8, 64), 256>>>(w_out, out);
}

// round 4
// speedup vs baseline: 1.5904x; 1.5904x over previous
#include <cuda_runtime.h>
#include <cuda_bf16.h>
#include <cstdint>
#include <math.h>

// ---------------------------------------------------------------------------
// Problem constants
// ---------------------------------------------------------------------------
#define BATCH    4
#define SEQ      2048
#define DMODEL   1024
#define NHEADS   16
#define HDIM     64
#define INV_SCALE 0.125f   // 1/sqrt(64)
#define NEG_INF_F (-1e30f)

#define MROWS   (BATCH * SEQ)       // 8192
#define NQKV    (3 * DMODEL)        // 3072

// ---------------------------------------------------------------------------
// Device scratch
// ---------------------------------------------------------------------------
__device__ float g_q[(size_t)BATCH * NHEADS * SEQ * HDIM];
__device__ float g_k[(size_t)BATCH * NHEADS * SEQ * HDIM];
__device__ float g_v[(size_t)BATCH * NHEADS * SEQ * HDIM];
__device__ float g_attn[(size_t)BATCH * SEQ * DMODEL];

// bf16 split operands
__device__ __nv_bfloat16 g_xhi[(size_t)MROWS * DMODEL];
__device__ __nv_bfloat16 g_xlo[(size_t)MROWS * DMODEL];
__device__ __nv_bfloat16 g_ahi[(size_t)MROWS * DMODEL];
__device__ __nv_bfloat16 g_alo[(size_t)MROWS * DMODEL];
// weights, split + transposed to [N][K]
__device__ __nv_bfloat16 g_wqh[(size_t)NQKV * DMODEL];
__device__ __nv_bfloat16 g_wql[(size_t)NQKV * DMODEL];
__device__ __nv_bfloat16 g_woh[(size_t)DMODEL * DMODEL];
__device__ __nv_bfloat16 g_wol[(size_t)DMODEL * DMODEL];

// ---------------------------------------------------------------------------
// Portable PTX helpers (mma.sync / ldmatrix — no 'a'-arch features)
// ---------------------------------------------------------------------------
__device__ __forceinline__ uint32_t smem_u32(const void* p) {
    uint32_t a;
    asm("{ .reg .u64 t; cvta.to.shared.u64 t, %1; cvt.u32.u64 %0, t; }"
        : "=r"(a) : "l"(p));
    return a;
}

__device__ __forceinline__ void ldm_x4(uint32_t* r, uint32_t addr) {
    asm volatile("ldmatrix.sync.aligned.m8n8.x4.shared.b16 {%0,%1,%2,%3}, [%4];"
                 : "=r"(r[0]), "=r"(r[1]), "=r"(r[2]), "=r"(r[3]) : "r"(addr));
}

__device__ __forceinline__ void mma16816(float* d, const uint32_t* a, const uint32_t* b) {
    asm volatile(
        "mma.sync.aligned.m16n8k16.row.col.f32.bf16.bf16.f32 "
        "{%0,%1,%2,%3}, {%4,%5,%6,%7}, {%8,%9}, {%0,%1,%2,%3};"
        : "+f"(d[0]), "+f"(d[1]), "+f"(d[2]), "+f"(d[3])
        : "r"(a[0]), "r"(a[1]), "r"(a[2]), "r"(a[3]), "r"(b[0]), "r"(b[1]));
}

// ---------------------------------------------------------------------------
// Conversion kernels: fp32 -> (hi, lo) bf16 split
// ---------------------------------------------------------------------------
__global__ __launch_bounds__(256) void convert_split_kernel(
    const float* __restrict__ src_arg, int sel, int n4)
{
    int i = blockIdx.x * 256 + threadIdx.x;
    if (i >= n4) return;
    const float* src = (sel == 0) ? src_arg : g_attn;
    __nv_bfloat16* hi = (sel == 0) ? g_xhi : g_ahi;
    __nv_bfloat16* lo = (sel == 0) ? g_xlo : g_alo;

    float4 v = ((const float4*)src)[i];
    __nv_bfloat16 h0 = __float2bfloat16_rn(v.x);
    __nv_bfloat16 h1 = __float2bfloat16_rn(v.y);
    __nv_bfloat16 h2 = __float2bfloat16_rn(v.z);
    __nv_bfloat16 h3 = __float2bfloat16_rn(v.w);
    __nv_bfloat16 l0 = __float2bfloat16_rn(v.x - __bfloat162float(h0));
    __nv_bfloat16 l1 = __float2bfloat16_rn(v.y - __bfloat162float(h1));
    __nv_bfloat16 l2 = __float2bfloat16_rn(v.z - __bfloat162float(h2));
    __nv_bfloat16 l3 = __float2bfloat16_rn(v.w - __bfloat162float(h3));
    __nv_bfloat162 ph0; ph0.x = h0; ph0.y = h1;
    __nv_bfloat162 ph1; ph1.x = h2; ph1.y = h3;
    __nv_bfloat162 pl0; pl0.x = l0; pl0.y = l1;
    __nv_bfloat162 pl1; pl1.x = l2; pl1.y = l3;
    ((__nv_bfloat162*)hi)[2 * i]     = ph0;
    ((__nv_bfloat162*)hi)[2 * i + 1] = ph1;
    ((__nv_bfloat162*)lo)[2 * i]     = pl0;
    ((__nv_bfloat162*)lo)[2 * i + 1] = pl1;
}

// W [K x N] fp32 -> transposed [N x K] bf16 hi/lo
__global__ __launch_bounds__(256) void transpose_split_kernel(
    const float* __restrict__ src, int sel, int N)
{
    __shared__ float tile[32][33];
    const int K = DMODEL;
    __nv_bfloat16* hi = (sel == 0) ? g_wqh : g_woh;
    __nv_bfloat16* lo = (sel == 0) ? g_wql : g_wol;

    int tx = threadIdx.x;          // 0..31
    int ty = threadIdx.y;          // 0..7
    int n0 = blockIdx.x * 32;
    int k0 = blockIdx.y * 32;

#pragma unroll
    for (int i = 0; i < 4; i++)
        tile[ty + 8 * i][tx] = src[(size_t)(k0 + ty + 8 * i) * N + n0 + tx];
    __syncthreads();
#pragma unroll
    for (int i = 0; i < 4; i++) {
        float v = tile[tx][ty + 8 * i];
        __nv_bfloat16 h = __float2bfloat16_rn(v);
        size_t o = (size_t)(n0 + ty + 8 * i) * K + k0 + tx;
        hi[o] = h;
        lo[o] = __float2bfloat16_rn(v - __bfloat162float(h));
    }
}

// ---------------------------------------------------------------------------
// mma.sync GEMM: C[M x NTOT] = A[M x 1024] * B^T (B stored [NTOT x 1024])
// bf16 split: hi*hi + hi*lo + lo*hi, fp32 acc in registers.
// CTA 128x128 tile, 256 threads (8 warps, 2x4), warp tile 64x32.
// K-chunk 64. Padded SMEM rows (72 bf16 = 144 B) -> conflict-free ldmatrix.
// MODE 0: scatter into g_q/g_k/g_v.  MODE 1: plain store into Cout.
// ---------------------------------------------------------------------------
#define ROWE 72               // bf16 elems per SMEM row (64 data + 8 pad)
#define ROWB (ROWE * 2)       // 144 bytes
#define TILE_BYTES (128 * ROWB)   // 18432
#define GEMM_SMEM_BYTES (4 * TILE_BYTES)  // 73728

template<int MODE>
__global__ __launch_bounds__(256) void mma_gemm_kernel(float* __restrict__ Cout)
{
    extern __shared__ char smem[];
    const uint32_t sbase = smem_u32(smem);
    const int OFF_AH = 0;
    const int OFF_AL = TILE_BYTES;
    const int OFF_BH = 2 * TILE_BYTES;
    const int OFF_BL = 3 * TILE_BYTES;

    const int tid  = threadIdx.x;
    const int wid  = tid >> 5;
    const int lane = tid & 31;
    const int wm   = wid >> 2;          // 0..1
    const int wn   = wid & 3;           // 0..3
    const int m0   = blockIdx.y * 128;
    const int n0   = blockIdx.x * 128;

    const __nv_bfloat16* Ahi = (MODE == 0) ? g_xhi : g_ahi;
    const __nv_bfloat16* Alo = (MODE == 0) ? g_xlo : g_alo;
    const __nv_bfloat16* Bhi = (MODE == 0) ? g_wqh : g_woh;
    const __nv_bfloat16* Blo = (MODE == 0) ? g_wql : g_wol;

    const uint4* A4h = (const uint4*)Ahi;   // row stride = 128 uint4 (1024 bf16)
    const uint4* A4l = (const uint4*)Alo;
    const uint4* B4h = (const uint4*)Bhi;
    const uint4* B4l = (const uint4*)Blo;

    float acc[4][4][4];
#pragma unroll
    for (int i = 0; i < 4; i++)
#pragma unroll
        for (int j = 0; j < 4; j++)
#pragma unroll
            for (int c = 0; c < 4; c++) acc[i][j][c] = 0.f;

    // ldmatrix base addresses (per-lane, k-step dependent part added in loop)
    // A frag (m16k16): row = wm*64 + mi*16 + (lane&15), col8 = (lane>>4)*8
    const int a_row = wm * 64 + (lane & 15);
    const int a_col = (lane >> 4) * 8;
    // B frag pair (n16k16): nrow = wn*32 + nb*16 + (lane&7) + ((lane>>4))*8,
    //                       kcol = ((lane>>3)&1)*8
    const int b_row = wn * 32 + (lane & 7) + (lane >> 4) * 8;
    const int b_col = ((lane >> 3) & 1) * 8;

    for (int kc = 0; kc < 16; kc++) {
        // ---- stage 4 tiles: 128 rows x 64 bf16 each ----
#pragma unroll
        for (int it = 0; it < 4; it++) {
            int e   = tid + it * 256;      // 0..1023
            int row = e >> 3;
            int seg = e & 7;
            uint32_t soff = (uint32_t)(row * ROWB + seg * 16);
            size_t aidx = (size_t)(m0 + row) * 128 + kc * 8 + seg;
            size_t bidx = (size_t)(n0 + row) * 128 + kc * 8 + seg;
            uint4 vah = A4h[aidx];
            uint4 val = A4l[aidx];
            uint4 vbh = B4h[bidx];
            uint4 vbl = B4l[bidx];
            *(uint4*)(smem + OFF_AH + soff) = vah;
            *(uint4*)(smem + OFF_AL + soff) = val;
            *(uint4*)(smem + OFF_BH + soff) = vbh;
            *(uint4*)(smem + OFF_BL + soff) = vbl;
        }
        __syncthreads();

        // ---- compute: 4 k-steps of 16 ----
#pragma unroll
        for (int ks = 0; ks < 4; ks++) {
            uint32_t a_addr = sbase + (uint32_t)(a_row * ROWB + (ks * 16 + a_col) * 2);
            uint32_t b_addr = sbase + (uint32_t)(b_row * ROWB + (ks * 16 + b_col) * 2);

            uint32_t af[4][4];          // A fragments (hi first, later overwritten by lo)
            uint32_t bh[4][2], bl[4][2];

#pragma unroll
            for (int mi = 0; mi < 4; mi++)
                ldm_x4(af[mi], a_addr + OFF_AH + mi * 16 * ROWB);
#pragma unroll
            for (int np = 0; np < 2; np++) {   // each x4 covers 2 n-frags
                uint32_t r[4];
                ldm_x4(r, b_addr + OFF_BH + np * 16 * ROWB);
                bh[np * 2][0] = r[0]; bh[np * 2][1] = r[1];
                bh[np * 2 + 1][0] = r[2]; bh[np * 2 + 1][1] = r[3];
                ldm_x4(r, b_addr + OFF_BL + np * 16 * ROWB);
                bl[np * 2][0] = r[0]; bl[np * 2][1] = r[1];
                bl[np * 2 + 1][0] = r[2]; bl[np * 2 + 1][1] = r[3];
            }

            // Ah * Bh
#pragma unroll
            for (int mi = 0; mi < 4; mi++)
#pragma unroll
                for (int ni = 0; ni < 4; ni++)
                    mma16816(acc[mi][ni], af[mi], bh[ni]);
            // Ah * Bl
#pragma unroll
            for (int mi = 0; mi < 4; mi++)
#pragma unroll
                for (int ni = 0; ni < 4; ni++)
                    mma16816(acc[mi][ni], af[mi], bl[ni]);
            // Al * Bh  (reload A frags as lo)
#pragma unroll
            for (int mi = 0; mi < 4; mi++)
                ldm_x4(af[mi], a_addr + OFF_AL + mi * 16 * ROWB);
#pragma unroll
            for (int mi = 0; mi < 4; mi++)
#pragma unroll
                for (int ni = 0; ni < 4; ni++)
                    mma16816(acc[mi][ni], af[mi], bh[ni]);
        }
        __syncthreads();
    }

    // ---- epilogue: acc layout: thread holds rows (lane>>2, +8), cols (lane&3)*2, +1
    const int er = lane >> 2;
    const int ec = (lane & 3) * 2;
#pragma unroll
    for (int mi = 0; mi < 4; mi++) {
#pragma unroll
        for (int rr = 0; rr < 2; rr++) {
            int m = m0 + wm * 64 + mi * 16 + er + rr * 8;
            int b = m >> 11;
            int s = m & 2047;
#pragma unroll
            for (int ni = 0; ni < 4; ni++) {
#pragma unroll
                for (int cc = 0; cc < 2; cc++) {
                    int n = n0 + wn * 32 + ni * 8 + ec + cc;
                    float v = acc[mi][ni][rr * 2 + cc];
                    if (MODE == 0) {
                        int t = n >> 10;
                        int h = (n >> 6) & 15;
                        int d = n & 63;
                        float* dst = (t == 0) ? g_q : (t == 1) ? g_k : g_v;
                        dst[(((size_t)(b * NHEADS + h) * SEQ) + s) * HDIM + d] = v;
                    } else {
                        Cout[(size_t)m * DMODEL + n] = v;
                    }
                }
            }
        }
    }
}

// ---------------------------------------------------------------------------
// Flash attention (fp32, online softmax) — unchanged from passing R1 kernel.
// ---------------------------------------------------------------------------
__global__ __launch_bounds__(64) void flash_attn_kernel(const int* __restrict__ mask)
{
    __shared__ float Ks[32][64];
    __shared__ float Vs[32][64];
    __shared__ int   Ms[32];

    int tid = threadIdx.x;
    int qb  = blockIdx.x;
    int bh  = blockIdx.y;
    int b   = bh >> 4;
    int h   = bh & 15;
    int r   = qb * 64 + tid;

    const float4* qptr = (const float4*)(g_q + ((size_t)bh * SEQ + r) * HDIM);
    float4 q[16];
#pragma unroll
    for (int i = 0; i < 16; i++) q[i] = qptr[i];

    float4 acc[16];
#pragma unroll
    for (int i = 0; i < 16; i++) acc[i] = make_float4(0.f, 0.f, 0.f, 0.f);

    float m_i = -1e38f;
    float l_i = 0.f;

    int nkb = qb * 2 + 2;
    for (int kb = 0; kb < nkb; kb++) {
        int j0 = kb * 32;
        const float4* K4 = (const float4*)(g_k + ((size_t)bh * SEQ + j0) * HDIM);
        const float4* V4 = (const float4*)(g_v + ((size_t)bh * SEQ + j0) * HDIM);
#pragma unroll
        for (int i = 0; i < 8; i++) {
            int idx = i * 64 + tid;
            ((float4*)Ks)[idx] = K4[idx];
            ((float4*)Vs)[idx] = V4[idx];
        }
        if (tid < 32) Ms[tid] = mask[b * SEQ + j0 + tid];
        __syncthreads();

        float sc[32];
        float bmax = -1e38f;
#pragma unroll 4
        for (int j = 0; j < 32; j++) {
            const float4* kr = (const float4*)&Ks[j][0];
            float4 s4 = make_float4(0.f, 0.f, 0.f, 0.f);
#pragma unroll
            for (int i = 0; i < 16; i++) {
                float4 k4 = kr[i];
                s4.x += q[i].x * k4.x;
                s4.y += q[i].y * k4.y;
                s4.z += q[i].z * k4.z;
                s4.w += q[i].w * k4.w;
            }
            float s = (s4.x + s4.y) + (s4.z + s4.w);
            s *= INV_SCALE;
            int kj = j0 + j;
            if (kj > r || Ms[j] == 0) s = NEG_INF_F;
            sc[j] = s;
            bmax = fmaxf(bmax, s);
        }

        float m_new = fmaxf(m_i, bmax);
        float scale = __expf(m_i - m_new);
        float lsum = 0.f;
#pragma unroll
        for (int j = 0; j < 32; j++) {
            float p = __expf(sc[j] - m_new);
            lsum += p;
            sc[j] = p;
        }
        l_i = l_i * scale + lsum;
#pragma unroll
        for (int i = 0; i < 16; i++) {
            acc[i].x *= scale; acc[i].y *= scale;
            acc[i].z *= scale; acc[i].w *= scale;
        }
#pragma unroll 4
        for (int j = 0; j < 32; j++) {
            float p = sc[j];
            const float4* vr = (const float4*)&Vs[j][0];
#pragma unroll
            for (int i = 0; i < 16; i++) {
                float4 v4 = vr[i];
                acc[i].x += p * v4.x;
                acc[i].y += p * v4.y;
                acc[i].z += p * v4.z;
                acc[i].w += p * v4.w;
            }
        }
        m_i = m_new;
        __syncthreads();
    }

    float inv_l = 1.f / l_i;
    float4* optr = (float4*)(g_attn + (((size_t)b * SEQ + r) * NHEADS + h) * HDIM);
#pragma unroll
    for (int i = 0; i < 16; i++) {
        float4 o = acc[i];
        o.x *= inv_l; o.y *= inv_l; o.z *= inv_l; o.w *= inv_l;
        optr[i] = o;
    }
}

// ---------------------------------------------------------------------------
// Entry point
// ---------------------------------------------------------------------------
extern "C" void kernel_launch(void* const* d_in, const int* in_sizes, int n_in,
                              void* d_out, int out_size)
{
    const float* x      = (const float*)d_in[0];   // (4, 2048, 1024) fp32
    const int*   mask   = (const int*)d_in[1];     // (4, 2048) int32
    const float* w_qkv  = (const float*)d_in[2];   // (1024, 3072) fp32
    const float* w_out  = (const float*)d_in[3];   // (1024, 1024) fp32
    float*       out    = (float*)d_out;           // (4, 2048, 1024) fp32

    (void)in_sizes; (void)n_in; (void)out_size;

    cudaFuncSetAttribute(mma_gemm_kernel<0>,
                         cudaFuncAttributeMaxDynamicSharedMemorySize, GEMM_SMEM_BYTES);
    cudaFuncSetAttribute(mma_gemm_kernel<1>,
                         cudaFuncAttributeMaxDynamicSharedMemorySize, GEMM_SMEM_BYTES);

    // prep: bf16 splits
    convert_split_kernel<<<(MROWS * DMODEL / 4 + 255) / 256, 256>>>(x, 0, MROWS * DMODEL / 4);
    transpose_split_kernel<<<dim3(NQKV / 32, DMODEL / 32), dim3(32, 8)>>>(w_qkv, 0, NQKV);
    transpose_split_kernel<<<dim3(DMODEL / 32, DMODEL / 32), dim3(32, 8)>>>(w_out, 1, DMODEL);

    // 1) QKV projection (tensor cores via mma.sync) -> g_q/g_k/g_v
    mma_gemm_kernel<0><<<dim3(NQKV / 128, MROWS / 128), 256, GEMM_SMEM_BYTES>>>(nullptr);

    // 2) Causal flash attention -> g_attn
    flash_attn_kernel<<<dim3(SEQ / 64, BATCH * NHEADS), 64>>>(mask);

    // 3) split attn output, output projection -> d_out
    convert_split_kernel<<<(MROWS * DMODEL / 4 + 255) / 256, 256>>>(nullptr, 1, MROWS * DMODEL / 4);
    mma_gemm_kernel<1><<<dim3(DMODEL / 128, MROWS / 128), 256, GEMM_SMEM_BYTES>>>(out);
}

// round 5
// speedup vs baseline: 3.4063x; 2.1417x over previous
#include <cuda_runtime.h>
#include <cuda_bf16.h>
#include <cstdint>
#include <math.h>

// ---------------------------------------------------------------------------
// Problem constants
// ---------------------------------------------------------------------------
#define BATCH    4
#define SEQ      2048
#define DMODEL   1024
#define NHEADS   16
#define HDIM     64
#define NEG_INF_F (-1e30f)

#define MROWS   (BATCH * SEQ)       // 8192
#define NQKV    (3 * DMODEL)        // 3072

// ---------------------------------------------------------------------------
// Device scratch (bf16 hi/lo splits everywhere)
// ---------------------------------------------------------------------------
__device__ __nv_bfloat16 g_xhi[(size_t)MROWS * DMODEL];
__device__ __nv_bfloat16 g_xlo[(size_t)MROWS * DMODEL];
__device__ __nv_bfloat16 g_ahi[(size_t)MROWS * DMODEL];
__device__ __nv_bfloat16 g_alo[(size_t)MROWS * DMODEL];
// weights, split + transposed to [N][K]
__device__ __nv_bfloat16 g_wqh[(size_t)NQKV * DMODEL];
__device__ __nv_bfloat16 g_wql[(size_t)NQKV * DMODEL];
__device__ __nv_bfloat16 g_woh[(size_t)DMODEL * DMODEL];
__device__ __nv_bfloat16 g_wol[(size_t)DMODEL * DMODEL];
// attention operands: Q (pre-scaled 1/8), K in [bh][s][d]; V transposed [bh][d][s]
__device__ __nv_bfloat16 g_qhi[(size_t)BATCH * NHEADS * SEQ * HDIM];
__device__ __nv_bfloat16 g_qlo[(size_t)BATCH * NHEADS * SEQ * HDIM];
__device__ __nv_bfloat16 g_khi[(size_t)BATCH * NHEADS * SEQ * HDIM];
__device__ __nv_bfloat16 g_klo[(size_t)BATCH * NHEADS * SEQ * HDIM];
__device__ __nv_bfloat16 g_vhi[(size_t)BATCH * NHEADS * HDIM * SEQ];
__device__ __nv_bfloat16 g_vlo[(size_t)BATCH * NHEADS * HDIM * SEQ];

// ---------------------------------------------------------------------------
// Portable PTX helpers (mma.sync / ldmatrix — compile for plain compute_103)
// ---------------------------------------------------------------------------
__device__ __forceinline__ uint32_t smem_u32(const void* p) {
    uint32_t a;
    asm("{ .reg .u64 t; cvta.to.shared.u64 t, %1; cvt.u32.u64 %0, t; }"
        : "=r"(a) : "l"(p));
    return a;
}

__device__ __forceinline__ void ldm_x4(uint32_t* r, uint32_t addr) {
    asm volatile("ldmatrix.sync.aligned.m8n8.x4.shared.b16 {%0,%1,%2,%3}, [%4];"
                 : "=r"(r[0]), "=r"(r[1]), "=r"(r[2]), "=r"(r[3]) : "r"(addr));
}

__device__ __forceinline__ void mma16816(float* d, const uint32_t* a, const uint32_t* b) {
    asm volatile(
        "mma.sync.aligned.m16n8k16.row.col.f32.bf16.bf16.f32 "
        "{%0,%1,%2,%3}, {%4,%5,%6,%7}, {%8,%9}, {%0,%1,%2,%3};"
        : "+f"(d[0]), "+f"(d[1]), "+f"(d[2]), "+f"(d[3])
        : "r"(a[0]), "r"(a[1]), "r"(a[2]), "r"(a[3]), "r"(b[0]), "r"(b[1]));
}

// pack two fp32 into bf16x2: upper = hi_val, lower = lo_val
__device__ __forceinline__ uint32_t cvt_bf16x2(float hi_val, float lo_val) {
    uint32_t r;
    asm("cvt.rn.bf16x2.f32 %0, %1, %2;" : "=r"(r) : "f"(hi_val), "f"(lo_val));
    return r;
}
__device__ __forceinline__ float bf16x2_lo(uint32_t v) {
    __nv_bfloat162 t = *(__nv_bfloat162*)&v; return __bfloat162float(t.x);
}
__device__ __forceinline__ float bf16x2_hi(uint32_t v) {
    __nv_bfloat162 t = *(__nv_bfloat162*)&v; return __bfloat162float(t.y);
}

// ---------------------------------------------------------------------------
// Conversion: x fp32 -> (hi, lo) bf16 split
// ---------------------------------------------------------------------------
__global__ __launch_bounds__(256) void convert_split_kernel(
    const float* __restrict__ src, int n4)
{
    int i = blockIdx.x * 256 + threadIdx.x;
    if (i >= n4) return;
    float4 v = ((const float4*)src)[i];
    __nv_bfloat16 h0 = __float2bfloat16_rn(v.x);
    __nv_bfloat16 h1 = __float2bfloat16_rn(v.y);
    __nv_bfloat16 h2 = __float2bfloat16_rn(v.z);
    __nv_bfloat16 h3 = __float2bfloat16_rn(v.w);
    __nv_bfloat162 ph0; ph0.x = h0; ph0.y = h1;
    __nv_bfloat162 ph1; ph1.x = h2; ph1.y = h3;
    __nv_bfloat162 pl0;
    pl0.x = __float2bfloat16_rn(v.x - __bfloat162float(h0));
    pl0.y = __float2bfloat16_rn(v.y - __bfloat162float(h1));
    __nv_bfloat162 pl1;
    pl1.x = __float2bfloat16_rn(v.z - __bfloat162float(h2));
    pl1.y = __float2bfloat16_rn(v.w - __bfloat162float(h3));
    ((__nv_bfloat162*)g_xhi)[2 * i]     = ph0;
    ((__nv_bfloat162*)g_xhi)[2 * i + 1] = ph1;
    ((__nv_bfloat162*)g_xlo)[2 * i]     = pl0;
    ((__nv_bfloat162*)g_xlo)[2 * i + 1] = pl1;
}

// W [K x N] fp32 -> transposed [N x K] bf16 hi/lo
__global__ __launch_bounds__(256) void transpose_split_kernel(
    const float* __restrict__ src, int sel, int N)
{
    __shared__ float tile[32][33];
    const int K = DMODEL;
    __nv_bfloat16* hi = (sel == 0) ? g_wqh : g_woh;
    __nv_bfloat16* lo = (sel == 0) ? g_wql : g_wol;

    int tx = threadIdx.x;
    int ty = threadIdx.y;
    int n0 = blockIdx.x * 32;
    int k0 = blockIdx.y * 32;

#pragma unroll
    for (int i = 0; i < 4; i++)
        tile[ty + 8 * i][tx] = src[(size_t)(k0 + ty + 8 * i) * N + n0 + tx];
    __syncthreads();
#pragma unroll
    for (int i = 0; i < 4; i++) {
        float v = tile[tx][ty + 8 * i];
        __nv_bfloat16 h = __float2bfloat16_rn(v);
        size_t o = (size_t)(n0 + ty + 8 * i) * K + k0 + tx;
        hi[o] = h;
        lo[o] = __float2bfloat16_rn(v - __bfloat162float(h));
    }
}

// ---------------------------------------------------------------------------
// mma.sync GEMM (as R3): CTA 128x128, 8 warps 2x4, warp 64x32, K-chunk 64.
// MODE 0: epilogue splits to bf16 hi/lo -> g_q*/g_k* ([bh][s][d]) and
//         g_v* transposed ([bh][d][s]); Q pre-scaled by 0.125.
// MODE 1: plain fp32 store into Cout.
// ---------------------------------------------------------------------------
#define ROWE 72
#define ROWB (ROWE * 2)
#define TILE_BYTES (128 * ROWB)
#define GEMM_SMEM_BYTES (4 * TILE_BYTES)

template<int MODE>
__global__ __launch_bounds__(256) void mma_gemm_kernel(float* __restrict__ Cout)
{
    extern __shared__ char smem[];
    const uint32_t sbase = smem_u32(smem);
    const int OFF_AH = 0;
    const int OFF_AL = TILE_BYTES;
    const int OFF_BH = 2 * TILE_BYTES;
    const int OFF_BL = 3 * TILE_BYTES;

    const int tid  = threadIdx.x;
    const int wid  = tid >> 5;
    const int lane = tid & 31;
    const int wm   = wid >> 2;
    const int wn   = wid & 3;
    const int m0   = blockIdx.y * 128;
    const int n0   = blockIdx.x * 128;

    const __nv_bfloat16* Ahi = (MODE == 0) ? g_xhi : g_ahi;
    const __nv_bfloat16* Alo = (MODE == 0) ? g_xlo : g_alo;
    const __nv_bfloat16* Bhi = (MODE == 0) ? g_wqh : g_woh;
    const __nv_bfloat16* Blo = (MODE == 0) ? g_wql : g_wol;

    const uint4* A4h = (const uint4*)Ahi;
    const uint4* A4l = (const uint4*)Alo;
    const uint4* B4h = (const uint4*)Bhi;
    const uint4* B4l = (const uint4*)Blo;

    float acc[4][4][4];
#pragma unroll
    for (int i = 0; i < 4; i++)
#pragma unroll
        for (int j = 0; j < 4; j++)
#pragma unroll
            for (int c = 0; c < 4; c++) acc[i][j][c] = 0.f;

    const int a_row = wm * 64 + (lane & 15);
    const int a_col = (lane >> 4) * 8;
    const int b_row = wn * 32 + (lane & 7) + (lane >> 4) * 8;
    const int b_col = ((lane >> 3) & 1) * 8;

    for (int kc = 0; kc < 16; kc++) {
#pragma unroll
        for (int it = 0; it < 4; it++) {
            int e   = tid + it * 256;
            int row = e >> 3;
            int seg = e & 7;
            uint32_t soff = (uint32_t)(row * ROWB + seg * 16);
            size_t aidx = (size_t)(m0 + row) * 128 + kc * 8 + seg;
            size_t bidx = (size_t)(n0 + row) * 128 + kc * 8 + seg;
            uint4 vah = A4h[aidx];
            uint4 val = A4l[aidx];
            uint4 vbh = B4h[bidx];
            uint4 vbl = B4l[bidx];
            *(uint4*)(smem + OFF_AH + soff) = vah;
            *(uint4*)(smem + OFF_AL + soff) = val;
            *(uint4*)(smem + OFF_BH + soff) = vbh;
            *(uint4*)(smem + OFF_BL + soff) = vbl;
        }
        __syncthreads();

#pragma unroll
        for (int ks = 0; ks < 4; ks++) {
            uint32_t a_addr = sbase + (uint32_t)(a_row * ROWB + (ks * 16 + a_col) * 2);
            uint32_t b_addr = sbase + (uint32_t)(b_row * ROWB + (ks * 16 + b_col) * 2);

            uint32_t af[4][4];
            uint32_t bh[4][2], bl[4][2];

#pragma unroll
            for (int mi = 0; mi < 4; mi++)
                ldm_x4(af[mi], a_addr + OFF_AH + mi * 16 * ROWB);
#pragma unroll
            for (int np = 0; np < 2; np++) {
                uint32_t r[4];
                ldm_x4(r, b_addr + OFF_BH + np * 16 * ROWB);
                bh[np * 2][0] = r[0]; bh[np * 2][1] = r[1];
                bh[np * 2 + 1][0] = r[2]; bh[np * 2 + 1][1] = r[3];
                ldm_x4(r, b_addr + OFF_BL + np * 16 * ROWB);
                bl[np * 2][0] = r[0]; bl[np * 2][1] = r[1];
                bl[np * 2 + 1][0] = r[2]; bl[np * 2 + 1][1] = r[3];
            }

#pragma unroll
            for (int mi = 0; mi < 4; mi++)
#pragma unroll
                for (int ni = 0; ni < 4; ni++)
                    mma16816(acc[mi][ni], af[mi], bh[ni]);
#pragma unroll
            for (int mi = 0; mi < 4; mi++)
#pragma unroll
                for (int ni = 0; ni < 4; ni++)
                    mma16816(acc[mi][ni], af[mi], bl[ni]);
#pragma unroll
            for (int mi = 0; mi < 4; mi++)
                ldm_x4(af[mi], a_addr + OFF_AL + mi * 16 * ROWB);
#pragma unroll
            for (int mi = 0; mi < 4; mi++)
#pragma unroll
                for (int ni = 0; ni < 4; ni++)
                    mma16816(acc[mi][ni], af[mi], bh[ni]);
        }
        __syncthreads();
    }

    const int er = lane >> 2;
    const int ec = (lane & 3) * 2;
#pragma unroll
    for (int mi = 0; mi < 4; mi++) {
#pragma unroll
        for (int rr = 0; rr < 2; rr++) {
            int m = m0 + wm * 64 + mi * 16 + er + rr * 8;
            int b = m >> 11;
            int s = m & 2047;
#pragma unroll
            for (int ni = 0; ni < 4; ni++) {
#pragma unroll
                for (int cc = 0; cc < 2; cc++) {
                    int n = n0 + wn * 32 + ni * 8 + ec + cc;
                    float v = acc[mi][ni][rr * 2 + cc];
                    if (MODE == 0) {
                        int t = n >> 10;
                        int h = (n >> 6) & 15;
                        int d = n & 63;
                        if (t == 0) v *= 0.125f;   // fold 1/sqrt(hd) into Q
                        __nv_bfloat16 hv = __float2bfloat16_rn(v);
                        __nv_bfloat16 lv = __float2bfloat16_rn(v - __bfloat162float(hv));
                        int bh_i = b * NHEADS + h;
                        if (t == 2) {
                            size_t o = ((size_t)bh_i * HDIM + d) * SEQ + s;
                            g_vhi[o] = hv; g_vlo[o] = lv;
                        } else {
                            size_t o = ((size_t)bh_i * SEQ + s) * HDIM + d;
                            if (t == 0) { g_qhi[o] = hv; g_qlo[o] = lv; }
                            else        { g_khi[o] = hv; g_klo[o] = lv; }
                        }
                    } else {
                        Cout[(size_t)m * DMODEL + n] = v;
                    }
                }
            }
        }
    }
}

// ---------------------------------------------------------------------------
// Tensorized flash attention.
// grid = (S/128, B*H); 256 threads = 8 warps; warp w owns query rows w*16..+15.
// Scores = Qh*Kh + Qh*Kl + Ql*Kh (fp32 acc); P split hi/lo in registers;
// PV = Ph*Vh + Pl*Vh + Ph*Vl. V stored transposed [d][s].
// Epilogue emits bf16 hi/lo (g_ahi/g_alo) for the output projection.
// ---------------------------------------------------------------------------
#define AQH_OFF   0
#define AQL_OFF   18432
#define AKH_OFF   36864
#define AKL_OFF   55296
#define AVH_OFF   73728
#define AVL_OFF   91136
#define ABIAS_OFF 108544
#define ATT_SMEM  109056
#define VROWB     272     // 128 keys * 2B + 16B pad

__global__ __launch_bounds__(256) void flash_attn_mma_kernel(const int* __restrict__ mask)
{
    extern __shared__ char smem[];
    const uint32_t sbase = smem_u32(smem);
    const int tid  = threadIdx.x;
    const int wid  = tid >> 5;
    const int lane = tid & 31;
    const int qb   = blockIdx.x;
    const int bh   = blockIdx.y;
    const int b    = bh >> 4;
    const int h    = bh & 15;
    const int q0   = qb * 128;
    const int r0   = wid * 16;
    const int er   = lane >> 2;
    const int ec   = (lane & 3) * 2;

    // load Q hi/lo tile (128 x 64)
    {
        const uint4* Qh4 = (const uint4*)(g_qhi + ((size_t)bh * SEQ + q0) * HDIM);
        const uint4* Ql4 = (const uint4*)(g_qlo + ((size_t)bh * SEQ + q0) * HDIM);
#pragma unroll
        for (int it = 0; it < 4; it++) {
            int e = tid + it * 256;
            int row = e >> 3, seg = e & 7;
            uint32_t soff = (uint32_t)(row * ROWB + seg * 16);
            *(uint4*)(smem + AQH_OFF + soff) = Qh4[row * 8 + seg];
            *(uint4*)(smem + AQL_OFF + soff) = Ql4[row * 8 + seg];
        }
    }

    float m_s[2] = {-1e30f, -1e30f};
    float l_s[2] = {0.f, 0.f};
    float o[8][4];
#pragma unroll
    for (int i = 0; i < 8; i++)
#pragma unroll
        for (int c = 0; c < 4; c++) o[i][c] = 0.f;

    const uint32_t a_base = sbase + (uint32_t)((r0 + (lane & 15)) * ROWB + ((lane >> 4) * 8) * 2);
    const uint32_t b_base = sbase + AKH_OFF +
        (uint32_t)(((lane & 7) + (lane >> 4) * 8) * ROWB + (((lane >> 3) & 1) * 8) * 2);
    const uint32_t v_base = sbase + AVH_OFF +
        (uint32_t)(((lane & 7) + (lane >> 4) * 8) * VROWB + (((lane >> 3) & 1) * 8) * 2);

    for (int kb = 0; kb <= qb; kb++) {
        const int j0 = kb * 128;
        // ---- stage K hi/lo (128 x 64) and V hi/lo (64 x 128) + mask bias ----
        {
            const uint4* Kh4 = (const uint4*)(g_khi + ((size_t)bh * SEQ + j0) * HDIM);
            const uint4* Kl4 = (const uint4*)(g_klo + ((size_t)bh * SEQ + j0) * HDIM);
#pragma unroll
            for (int it = 0; it < 4; it++) {
                int e = tid + it * 256;
                int row = e >> 3, seg = e & 7;
                uint32_t soff = (uint32_t)(row * ROWB + seg * 16);
                *(uint4*)(smem + AKH_OFF + soff) = Kh4[row * 8 + seg];
                *(uint4*)(smem + AKL_OFF + soff) = Kl4[row * 8 + seg];
            }
#pragma unroll
            for (int it = 0; it < 4; it++) {
                int e = tid + it * 256;
                int d = e >> 4, seg = e & 15;
                uint32_t soff = (uint32_t)(d * VROWB + seg * 16);
                size_t gi = (((size_t)(bh * HDIM + d) * SEQ + j0) >> 3) + seg;
                *(uint4*)(smem + AVH_OFF + soff) = ((const uint4*)g_vhi)[gi];
                *(uint4*)(smem + AVL_OFF + soff) = ((const uint4*)g_vlo)[gi];
            }
            if (tid < 128)
                *(float*)(smem + ABIAS_OFF + tid * 4) =
                    (mask[b * SEQ + j0 + tid] == 0) ? NEG_INF_F : 0.f;
        }
        __syncthreads();

        // ---- scores: 16 n-frags x 4 k-steps x 3 splits ----
        float sc[16][4];
#pragma unroll
        for (int i = 0; i < 16; i++)
#pragma unroll
            for (int c = 0; c < 4; c++) sc[i][c] = 0.f;

#pragma unroll
        for (int ks = 0; ks < 4; ks++) {
            uint32_t qh[4], ql[4];
            ldm_x4(qh, a_base + AQH_OFF + ks * 32);
            ldm_x4(ql, a_base + AQL_OFF + ks * 32);
#pragma unroll
            for (int np = 0; np < 8; np++) {
                uint32_t kh[4], kl[4];
                ldm_x4(kh, b_base + ks * 32 + np * 16 * ROWB);
                ldm_x4(kl, b_base + (AKL_OFF - AKH_OFF) + ks * 32 + np * 16 * ROWB);
                mma16816(sc[2 * np],     qh, kh);
                mma16816(sc[2 * np + 1], qh, kh + 2);
                mma16816(sc[2 * np],     qh, kl);
                mma16816(sc[2 * np + 1], qh, kl + 2);
                mma16816(sc[2 * np],     ql, kh);
                mma16816(sc[2 * np + 1], ql, kh + 2);
            }
        }

        // ---- pad-mask bias + causal (diagonal block only) ----
#pragma unroll
        for (int nf = 0; nf < 16; nf++) {
            float2 bv = *(const float2*)(smem + ABIAS_OFF + (nf * 8 + ec) * 4);
            sc[nf][0] += bv.x; sc[nf][1] += bv.y;
            sc[nf][2] += bv.x; sc[nf][3] += bv.y;
        }
        if (kb == qb) {
            int rl0 = r0 + er, rl1 = r0 + er + 8;
#pragma unroll
            for (int nf = 0; nf < 16; nf++) {
                int c0 = nf * 8 + ec, c1 = c0 + 1;
                if (c0 > rl0) sc[nf][0] = NEG_INF_F;
                if (c1 > rl0) sc[nf][1] = NEG_INF_F;
                if (c0 > rl1) sc[nf][2] = NEG_INF_F;
                if (c1 > rl1) sc[nf][3] = NEG_INF_F;
            }
        }

        // ---- online softmax (rows er / er+8; reduce over lane quads) ----
#pragma unroll
        for (int rr = 0; rr < 2; rr++) {
            float bm = -1e30f;
#pragma unroll
            for (int nf = 0; nf < 16; nf++)
                bm = fmaxf(bm, fmaxf(sc[nf][rr * 2], sc[nf][rr * 2 + 1]));
            bm = fmaxf(bm, __shfl_xor_sync(0xffffffffu, bm, 1));
            bm = fmaxf(bm, __shfl_xor_sync(0xffffffffu, bm, 2));
            float m_new = fmaxf(fmaxf(m_s[rr], bm), -1e29f);
            float alpha = __expf(m_s[rr] - m_new);
            float ls = 0.f;
#pragma unroll
            for (int nf = 0; nf < 16; nf++) {
                float p0 = __expf(sc[nf][rr * 2]     - m_new);
                float p1 = __expf(sc[nf][rr * 2 + 1] - m_new);
                sc[nf][rr * 2] = p0; sc[nf][rr * 2 + 1] = p1;
                ls += p0 + p1;
            }
            ls += __shfl_xor_sync(0xffffffffu, ls, 1);
            ls += __shfl_xor_sync(0xffffffffu, ls, 2);
            l_s[rr] = l_s[rr] * alpha + ls;
            m_s[rr] = m_new;
#pragma unroll
            for (int nf = 0; nf < 8; nf++) {
                o[nf][rr * 2] *= alpha; o[nf][rr * 2 + 1] *= alpha;
            }
        }

        // ---- PV: P (regs) hi/lo x V(T) hi/lo ----
#pragma unroll
        for (int ks = 0; ks < 8; ks++) {
            uint32_t ah[4], al[4];
            ah[0] = cvt_bf16x2(sc[2 * ks][1], sc[2 * ks][0]);
            ah[1] = cvt_bf16x2(sc[2 * ks][3], sc[2 * ks][2]);
            ah[2] = cvt_bf16x2(sc[2 * ks + 1][1], sc[2 * ks + 1][0]);
            ah[3] = cvt_bf16x2(sc[2 * ks + 1][3], sc[2 * ks + 1][2]);
            al[0] = cvt_bf16x2(sc[2 * ks][1] - bf16x2_hi(ah[0]),
                               sc[2 * ks][0] - bf16x2_lo(ah[0]));
            al[1] = cvt_bf16x2(sc[2 * ks][3] - bf16x2_hi(ah[1]),
                               sc[2 * ks][2] - bf16x2_lo(ah[1]));
            al[2] = cvt_bf16x2(sc[2 * ks + 1][1] - bf16x2_hi(ah[2]),
                               sc[2 * ks + 1][0] - bf16x2_lo(ah[2]));
            al[3] = cvt_bf16x2(sc[2 * ks + 1][3] - bf16x2_hi(ah[3]),
                               sc[2 * ks + 1][2] - bf16x2_lo(ah[3]));
#pragma unroll
            for (int np = 0; np < 4; np++) {
                uint32_t vh[4], vl[4];
                ldm_x4(vh, v_base + ks * 32 + np * 16 * VROWB);
                ldm_x4(vl, v_base + (AVL_OFF - AVH_OFF) + ks * 32 + np * 16 * VROWB);
                mma16816(o[2 * np],     ah, vh);
                mma16816(o[2 * np + 1], ah, vh + 2);
                mma16816(o[2 * np],     al, vh);
                mma16816(o[2 * np + 1], al, vh + 2);
                mma16816(o[2 * np],     ah, vl);
                mma16816(o[2 * np + 1], ah, vl + 2);
            }
        }
        __syncthreads();
    }

    // ---- epilogue: normalize, split to bf16 hi/lo, store (B,S,D) ----
#pragma unroll
    for (int rr = 0; rr < 2; rr++) {
        float inv = 1.f / l_s[rr];
        int row = q0 + r0 + er + rr * 8;
        size_t base = ((size_t)b * SEQ + row) * DMODEL + h * HDIM;
#pragma unroll
        for (int nf = 0; nf < 8; nf++) {
            int d = nf * 8 + ec;
            float v0 = o[nf][rr * 2] * inv;
            float v1 = o[nf][rr * 2 + 1] * inv;
            __nv_bfloat162 hh;
            hh.x = __float2bfloat16_rn(v0);
            hh.y = __float2bfloat16_rn(v1);
            __nv_bfloat162 ll;
            ll.x = __float2bfloat16_rn(v0 - __bfloat162float(hh.x));
            ll.y = __float2bfloat16_rn(v1 - __bfloat162float(hh.y));
            *(__nv_bfloat162*)(g_ahi + base + d) = hh;
            *(__nv_bfloat162*)(g_alo + base + d) = ll;
        }
    }
}

// ---------------------------------------------------------------------------
// Entry point
// ---------------------------------------------------------------------------
extern "C" void kernel_launch(void* const* d_in, const int* in_sizes, int n_in,
                              void* d_out, int out_size)
{
    const float* x      = (const float*)d_in[0];   // (4, 2048, 1024) fp32
    const int*   mask   = (const int*)d_in[1];     // (4, 2048) int32
    const float* w_qkv  = (const float*)d_in[2];   // (1024, 3072) fp32
    const float* w_out  = (const float*)d_in[3];   // (1024, 1024) fp32
    float*       out    = (float*)d_out;           // (4, 2048, 1024) fp32

    (void)in_sizes; (void)n_in; (void)out_size;

    cudaFuncSetAttribute(mma_gemm_kernel<0>,
                         cudaFuncAttributeMaxDynamicSharedMemorySize, GEMM_SMEM_BYTES);
    cudaFuncSetAttribute(mma_gemm_kernel<1>,
                         cudaFuncAttributeMaxDynamicSharedMemorySize, GEMM_SMEM_BYTES);
    cudaFuncSetAttribute(flash_attn_mma_kernel,
                         cudaFuncAttributeMaxDynamicSharedMemorySize, ATT_SMEM);

    // prep: bf16 splits
    convert_split_kernel<<<(MROWS * DMODEL / 4 + 255) / 256, 256>>>(x, MROWS * DMODEL / 4);
    transpose_split_kernel<<<dim3(NQKV / 32, DMODEL / 32), dim3(32, 8)>>>(w_qkv, 0, NQKV);
    transpose_split_kernel<<<dim3(DMODEL / 32, DMODEL / 32), dim3(32, 8)>>>(w_out, 1, DMODEL);

    // 1) QKV projection -> q/k hi/lo [bh][s][d], v hi/lo transposed [bh][d][s]
    mma_gemm_kernel<0><<<dim3(NQKV / 128, MROWS / 128), 256, GEMM_SMEM_BYTES>>>(nullptr);

    // 2) Tensorized causal flash attention -> g_ahi/g_alo (B,S,D)
    flash_attn_mma_kernel<<<dim3(SEQ / 128, BATCH * NHEADS), 256, ATT_SMEM>>>(mask);

    // 3) Output projection -> d_out
    mma_gemm_kernel<1><<<dim3(DMODEL / 128, MROWS / 128), 256, GEMM_SMEM_BYTES>>>(out);
}